// round 2
// baseline (speedup 1.0000x reference)
#include <cuda_runtime.h>
#include <cstdint>
#include <math.h>

// CTRNN persistent kernel: B=128, N=512, T=1024, fp32 throughout.
// Grid = 128 CTAs (8 batch-chunks x 16 hidden-chunks), all co-resident on
// 148 SMs -> custom spin grid-barrier (1 per step) is safe.
// J slice cached in SMEM for the whole run; tanh(h) broadcast per step via a
// double-buffered __device__ scratch; inner product uses packed fma.rn.f32x2
// (2x fp32 FMA throughput vs scalar FFMA on Blackwell).

#define T_STEPS 1024
#define BATCH   128
#define NH      512
#define DTC     0.02f

#define HC   16              // hidden chunks
#define BC   8               // batch chunks
#define BS   (BATCH / BC)    // 16 batch rows per CTA
#define IS   (NH / HC)       // 32 hidden units per CTA
#define NCTA (HC * BC)       // 128
#define NTHR 256
#define KW   8               // k-split: 8 warps, 64 j's each
#define KCH  (NH / KW)       // 64
#define LDP  516             // padded smem row (floats) -> conflict-free strided loads

// Global scratch (allowed: __device__ globals, zero-initialized BSS)
__device__ float    g_th[2][BATCH][NH];      // tanh(h) double buffer
__device__ float    g_part[2][HC][BATCH];    // readout partials double buffer
__device__ unsigned g_barcnt;
__device__ unsigned g_bargen;

__device__ __forceinline__ unsigned long long ffma2(unsigned long long a,
                                                    unsigned long long b,
                                                    unsigned long long c) {
    unsigned long long d;
    asm("fma.rn.f32x2 %0, %1, %2, %3;" : "=l"(d) : "l"(a), "l"(b), "l"(c));
    return d;
}

__device__ __forceinline__ float2 unpack2(unsigned long long v) {
    float2 f;
    asm("mov.b64 {%0, %1}, %2;" : "=f"(f.x), "=f"(f.y) : "l"(v));
    return f;
}

__device__ __forceinline__ void grid_barrier() {
    __syncthreads();
    if (threadIdx.x == 0) {
        __threadfence();
        volatile unsigned* vg = &g_bargen;
        unsigned old = *vg;
        if (atomicAdd(&g_barcnt, 1u) == NCTA - 1) {
            g_barcnt = 0;
            __threadfence();
            atomicExch((unsigned*)&g_bargen, old + 1u);
        } else {
            while (*vg == old) { __nanosleep(32); }
        }
        __threadfence();
    }
    __syncthreads();
}

extern "C" __global__ void __launch_bounds__(NTHR, 1)
ctrnn_persistent_kernel(const float* __restrict__ vel,
                        const float* __restrict__ J,
                        const float* __restrict__ Bmat,
                        const float* __restrict__ Wro,
                        float* __restrict__ out) {
    extern __shared__ float smem[];
    float* J_s  = smem;                     // IS * LDP = 16512 floats
    float* th_s = J_s + IS * LDP;           // BS * LDP = 8256
    float* red  = th_s + BS * LDP;          // KW * BS * IS = 4096
    float* h_s  = red + KW * BS * IS;       // BS * IS = 512
    float* v_s  = h_s + BS * IS;            // BS
    float* bm_s = v_s + BS;                 // IS
    float* wr_s = bm_s + IS;                // IS

    const int tid = threadIdx.x;
    const int hc  = blockIdx.x % HC;
    const int bc  = blockIdx.x / HC;
    const int b0  = bc * BS;
    const int i0  = hc * IS;

    // Load this CTA's J slice [IS x NH] into padded SMEM (read from HBM once).
    for (int k = tid * 4; k < IS * NH; k += NTHR * 4) {
        int r = k / NH, c = k % NH;
        float4 v4 = *reinterpret_cast<const float4*>(J + (size_t)(i0 + r) * NH + c);
        *reinterpret_cast<float4*>(J_s + r * LDP + c) = v4;
    }
    if (tid < IS) {
        bm_s[tid] = Bmat[i0 + tid];
        wr_s[tid] = Wro[i0 + tid];
    }
    for (int k = tid; k < BS * IS; k += NTHR) h_s[k] = 0.0f;
    __syncthreads();

    const int w     = tid >> 5;     // warp -> k-chunk
    const int lane  = tid & 31;
    const int bg    = lane & 3;     // 4 b-groups
    const int ig    = lane >> 2;    // 8 i-groups
    const int kbase = w * KCH;

    for (int t = 0; t < T_STEPS; ++t) {
        const int p = t & 1;

        // Deterministic lagged readout: write out[:, t-1] (hc==0 CTAs only).
        if (hc == 0 && t > 0 && tid < BS) {
            float s = 0.f;
            #pragma unroll
            for (int k = 0; k < HC; ++k) s += g_part[(t - 1) & 1][k][b0 + tid];
            out[(size_t)(b0 + tid) * T_STEPS + (t - 1)] = s;
        }

        // Stage tanh(h_{t-1}) for our batch slice into SMEM.
        if (t == 0) {
            for (int k = tid * 4; k < BS * NH; k += NTHR * 4) {
                int r = k / NH, c = k % NH;
                *reinterpret_cast<float4*>(th_s + r * LDP + c) =
                    make_float4(0.f, 0.f, 0.f, 0.f);
            }
        } else {
            for (int k = tid * 4; k < BS * NH; k += NTHR * 4) {
                int r = k / NH, c = k % NH;
                float4 v4 = *reinterpret_cast<const float4*>(&g_th[p][b0 + r][c]);
                *reinterpret_cast<float4*>(th_s + r * LDP + c) = v4;
            }
        }
        if (tid < BS) v_s[tid] = vel[(size_t)(b0 + tid) * T_STEPS + t];
        __syncthreads();

        // GEMM: mv[b][i] = sum_j th[b][j] * J[i][j]; k split across 8 warps,
        // thread tile 4b x 4i, packed f32x2 over j.
        unsigned long long acc0[4][4], acc1[4][4];
        #pragma unroll
        for (int u = 0; u < 4; ++u)
            #pragma unroll
            for (int v = 0; v < 4; ++v) { acc0[u][v] = 0ull; acc1[u][v] = 0ull; }

        #pragma unroll 4
        for (int jt = 0; jt < KCH; jt += 4) {
            const int j = kbase + jt;
            ulonglong2 av[4], bv[4];
            #pragma unroll
            for (int u = 0; u < 4; ++u)
                av[u] = *reinterpret_cast<const ulonglong2*>(th_s + (bg + 4 * u) * LDP + j);
            #pragma unroll
            for (int v = 0; v < 4; ++v)
                bv[v] = *reinterpret_cast<const ulonglong2*>(J_s + (ig + 8 * v) * LDP + j);
            #pragma unroll
            for (int u = 0; u < 4; ++u)
                #pragma unroll
                for (int v = 0; v < 4; ++v) {
                    acc0[u][v] = ffma2(av[u].x, bv[v].x, acc0[u][v]);
                    acc1[u][v] = ffma2(av[u].y, bv[v].y, acc1[u][v]);
                }
        }
        #pragma unroll
        for (int u = 0; u < 4; ++u)
            #pragma unroll
            for (int v = 0; v < 4; ++v) {
                float2 lo = unpack2(acc0[u][v]);
                float2 hi = unpack2(acc1[u][v]);
                red[w * (BS * IS) + (bg + 4 * u) * IS + (ig + 8 * v)] =
                    (lo.x + lo.y) + (hi.x + hi.y);
            }
        __syncthreads();

        // Reduce k-partials, update h, tanh, publish th + readout partials.
        for (int idx = tid; idx < BS * IS; idx += NTHR) {
            float s = 0.f;
            #pragma unroll
            for (int k = 0; k < KW; ++k) s += red[k * (BS * IS) + idx];
            int b = idx / IS, i = idx - b * IS;
            float h = h_s[idx] * (1.0f - DTC) + DTC * (s + v_s[b] * bm_s[i]);
            h_s[idx] = h;
            float th = tanhf(h);
            g_th[p ^ 1][b0 + b][i0 + i] = th;
            red[idx] = th * wr_s[i];   // safe: each thread reads its own slice-0
        }                              // entries before overwriting them
        __syncthreads();
        if (tid < BS) {
            float s = 0.f;
            #pragma unroll
            for (int i = 0; i < IS; ++i) s += red[tid * IS + i];
            g_part[p][hc][b0 + tid] = s;
        }

        grid_barrier();
    }

    // Flush readout for the final step.
    if (hc == 0 && tid < BS) {
        float s = 0.f;
        #pragma unroll
        for (int k = 0; k < HC; ++k) s += g_part[(T_STEPS - 1) & 1][k][b0 + tid];
        out[(size_t)(b0 + tid) * T_STEPS + (T_STEPS - 1)] = s;
    }
}

#define SMEM_BYTES ((IS * LDP + BS * LDP + KW * BS * IS + BS * IS + BS + IS + IS) * 4)

extern "C" void kernel_launch(void* const* d_in, const int* in_sizes, int n_in,
                              void* d_out, int out_size) {
    const float* vel  = (const float*)d_in[0];   // [128,1024,1]
    const float* J    = (const float*)d_in[1];   // [512,512]
    const float* Bmat = (const float*)d_in[2];   // [512,1]
    const float* Wro  = (const float*)d_in[3];   // [1,512]
    float* out = (float*)d_out;                  // [128,1024,1]

    cudaFuncSetAttribute(ctrnn_persistent_kernel,
                         cudaFuncAttributeMaxDynamicSharedMemorySize, SMEM_BYTES);
    ctrnn_persistent_kernel<<<NCTA, NTHR, SMEM_BYTES>>>(vel, J, Bmat, Wro, out);
}